// round 1
// baseline (speedup 1.0000x reference)
#include <cuda_runtime.h>
#include <cuda_bf16.h>
#include <math.h>

// Problem constants (ImprovedLoss: B=64, H=W=80, C=80, T=50)
#define BB   64
#define HH   80
#define WW   80
#define HWC  (HH * WW)        // 6400 cells per image
#define NC   80               // classes
#define DD   (5 + NC)         // 85 channels
#define TT   50               // targets per image
#define NCELL ((long long)BB * HWC)   // 409600

#define NBLK 512
#define NTHR 256
#define NWARP (NTHR / 32)

#define LAMBDA_COORD 5.0
#define LAMBDA_NOOBJ 0.5

// Per-block partials (each block WRITES its own slot -> no zero-init needed).
// Fields: 0=xy 1=wh 2=cls 3=obj_neg(softplus(-c)) 4=obj_pos(softplus(c)) 5=conf_all 6=n_obj
__device__ double g_part[7][NBLK];
__device__ unsigned int g_done = 0;

__device__ __forceinline__ float softplusf(float x) {
    // logaddexp(x, 0) = max(x,0) + log1p(exp(-|x|))  (matches jax.nn.softplus)
    return log1pf(expf(-fabsf(x))) + fmaxf(x, 0.0f);
}

__device__ __forceinline__ double warp_sum_d(double v) {
#pragma unroll
    for (int o = 16; o; o >>= 1) v += __shfl_xor_sync(0xffffffffu, v, o);
    return v;
}
__device__ __forceinline__ float warp_max_f(float v) {
#pragma unroll
    for (int o = 16; o; o >>= 1) v = fmaxf(v, __shfl_xor_sync(0xffffffffu, v, o));
    return v;
}
__device__ __forceinline__ float warp_sum_f(float v) {
#pragma unroll
    for (int o = 16; o; o >>= 1) v += __shfl_xor_sync(0xffffffffu, v, o);
    return v;
}

__global__ void __launch_bounds__(NTHR)
improved_loss_kernel(const float* __restrict__ pred,
                     const float* __restrict__ targ,
                     float* __restrict__ out) {
    __shared__ int   gi_s[TT];
    __shared__ float tx_s[TT], ty_s[TT], tw_s[TT], th_s[TT];
    __shared__ int   cid_s[TT];
    __shared__ double sm_acc[7];
    __shared__ bool  is_last;

    const int tid  = threadIdx.x;
    const int bid  = blockIdx.x;
    const int lane = tid & 31;
    const int wid  = tid >> 5;

    if (tid < 7) sm_acc[tid] = 0.0;

    const bool targ_block = (bid < BB);
    if (targ_block && tid < TT) {
        const float* tp = targ + ((size_t)bid * TT + tid) * 5;
        float cid = tp[0], cx = tp[1], cy = tp[2], w = tp[3], h = tp[4];
        float fgx = floorf(cx * (float)WW);
        float fgy = floorf(cy * (float)HH);
        int gx = (int)fgx, gy = (int)fgy;
        gi_s[tid]  = gy * WW + gx;
        tx_s[tid]  = cx * (float)WW - fgx;
        ty_s[tid]  = cy * (float)HH - fgy;
        tw_s[tid]  = logf(w * (float)WW + 1e-16f);
        th_s[tid]  = logf(h * (float)HH + 1e-16f);
        cid_s[tid] = (int)cid;
    }
    __syncthreads();

    // ---------------- Dense pass: sum softplus(conf) over ALL cells ----------------
    double csum = 0.0;
    for (long long i = (long long)bid * NTHR + tid; i < NCELL; i += (long long)NBLK * NTHR) {
        float conf = __ldg(pred + (size_t)i * DD + 4);
        csum += (double)softplusf(conf);
    }
    csum = warp_sum_d(csum);
    if (lane == 0) atomicAdd(&sm_acc[5], csum);

    // ---------------- Sparse pass: per-target (blocks 0..B-1), 1 warp/target -------
    if (targ_block) {
        double xy = 0.0, wh = 0.0, cls = 0.0, oneg = 0.0, opos = 0.0, nobj = 0.0;
        for (int t = wid; t < TT; t += NWARP) {
            const int gi = gi_s[t];
            const float* p = pred + ((size_t)bid * HWC + gi) * DD;

            // log-sum-exp over 80 class logits p[5..84], 32 lanes cooperative
            float v0 = p[5 + lane];
            float v1 = p[5 + 32 + lane];
            float v2 = (lane < 16) ? p[5 + 64 + lane] : -INFINITY;
            float m  = warp_max_f(fmaxf(fmaxf(v0, v1), v2));
            float s  = expf(v0 - m) + expf(v1 - m) + ((lane < 16) ? expf(v2 - m) : 0.0f);
            s = warp_sum_f(s);

            if (lane == 0) {
                float lse = m + logf(s);
                float p0 = p[0], p1 = p[1], p2 = p[2], p3 = p[3], p4 = p[4];
                float sx = 1.0f / (1.0f + expf(-p0));
                float sy = 1.0f / (1.0f + expf(-p1));
                float dx = sx - tx_s[t], dy = sy - ty_s[t];
                xy += 0.5 * ((double)dx * dx + (double)dy * dy);
                float dw = p2 - tw_s[t], dh = p3 - th_s[t];
                wh += 0.5 * ((double)dw * dw + (double)dh * dh);
                cls += (double)(lse - p[5 + cid_s[t]]);
                // dedup: this target owns the obj cell iff no earlier target shares gi
                bool first = true;
                for (int u = 0; u < t; ++u)
                    if (gi_s[u] == gi) { first = false; break; }
                if (first) {
                    oneg += (double)softplusf(-p4);
                    opos += (double)softplusf(p4);
                    nobj += 1.0;
                }
            }
        }
        if (lane == 0) {
            atomicAdd(&sm_acc[0], xy);
            atomicAdd(&sm_acc[1], wh);
            atomicAdd(&sm_acc[2], cls);
            atomicAdd(&sm_acc[3], oneg);
            atomicAdd(&sm_acc[4], opos);
            atomicAdd(&sm_acc[6], nobj);
        }
    }

    __syncthreads();
    if (tid < 7) {
        g_part[tid][bid] = sm_acc[tid];
        __threadfence();
    }
    __syncthreads();

    if (tid == 0) {
        unsigned int v = atomicAdd(&g_done, 1u);
        is_last = (v == (unsigned int)(NBLK - 1));
    }
    __syncthreads();

    // ---------------- Finalize (last block only) ----------------
    if (is_last) {
        __threadfence();
        if (wid < 7) {
            double s = 0.0;
            for (int j = lane; j < NBLK; j += 32) s += g_part[wid][j];
            s = warp_sum_d(s);
            if (lane == 0) sm_acc[wid] = s;   // safe: past the syncthreads above
        }
        __syncthreads();
        if (tid == 0) {
            double xy = sm_acc[0], wh = sm_acc[1], cls = sm_acc[2];
            double oneg = sm_acc[3], opos = sm_acc[4], call = sm_acc[5], nobj = sm_acc[6];
            double n_noobj = (double)NCELL - nobj;
            double num_obj = (double)(BB * TT);
            double conf_obj   = oneg / fmax(nobj, 1.0);
            double conf_noobj = (call - opos) / fmax(n_noobj, 1.0);
            double total = LAMBDA_COORD * (xy + wh) / num_obj
                         + conf_obj / num_obj
                         + LAMBDA_NOOBJ * conf_noobj / fmax(n_noobj, 1.0)
                         + cls / num_obj;
            *out = (float)total;
            g_done = 0;   // reset for next graph replay (deterministic)
        }
    }
}

extern "C" void kernel_launch(void* const* d_in, const int* in_sizes, int n_in,
                              void* d_out, int out_size) {
    const float* pred = (const float*)d_in[0];
    const float* targ = (const float*)d_in[1];
    (void)in_sizes; (void)n_in; (void)out_size;
    improved_loss_kernel<<<NBLK, NTHR>>>(pred, targ, (float*)d_out);
}